// round 2
// baseline (speedup 1.0000x reference)
#include <cuda_runtime.h>

typedef unsigned long long ull;

#define DECAYF 0.99f
#define OMDF   0.01f
#define EPSF   1e-5f

constexpr int C_ = 64, K_ = 512, B_ = 64, H_ = 64, W_ = 64;
constexpr int HW_  = H_ * W_;          // 4096
constexpr int CHW_ = C_ * HW_;         // 262144
constexpr int NROWS_ = B_ * H_;        // 4096
constexpr int NPTS_  = NROWS_ * W_;    // 262144

constexpr int EPAD = 66;               // padded row stride for e_sh (bank-friendly, 8B aligned)
constexpr int XPAD = 66;

constexpr int SM_FLOATS = K_ * EPAD     // e_sh
                        + K_            // esq
                        + W_ * XPAD     // x_sh
                        + 64 * 8        // redv
                        + 64 * 8        // redk
                        + 64            // ind_sh
                        + K_            // hist
                        + 1;            // diff_sh
constexpr int SMEM_BYTES = SM_FLOATS * 4;   // ~157 KB, fits 228 KB carveout at 1 CTA/SM

// Output layout (concatenated, float32, reference return order):
// out[B,C,H,W], diff, embedding_ind[B,H,W], new_embedding[C,K],
// new_cluster_size[K], new_embedding_avg[C,K]
constexpr long long OFF_DIFF = (long long)B_ * C_ * H_ * W_;   // 16777216
constexpr long long OFF_IND  = OFF_DIFF + 1;                   // 16777217
constexpr long long OFF_EMB  = OFF_IND + (long long)NPTS_;     // 17039361
constexpr long long OFF_CS   = OFF_EMB + (long long)C_ * K_;   // 17072129
constexpr long long OFF_AVG  = OFF_CS + K_;                    // 17072641

// scratch (no allocations allowed -> device globals)
__device__ float g_esum[C_ * K_];
__device__ float g_counts[K_];
__device__ float g_diff;

__device__ __forceinline__ void fma2(ull& d, ull a, ull b) {
    asm("fma.rn.f32x2 %0, %1, %2, %0;" : "+l"(d) : "l"(a), "l"(b));
}
__device__ __forceinline__ float2 u2f(ull u) {
    float2 f; asm("mov.b64 {%0, %1}, %2;" : "=f"(f.x), "=f"(f.y) : "l"(u)); return f;
}

__global__ void vq_init() {
    int i = blockIdx.x * blockDim.x + threadIdx.x;
    const int tot = C_ * K_ + K_ + 1;
    for (; i < tot; i += gridDim.x * blockDim.x) {
        if (i < C_ * K_)            g_esum[i] = 0.f;
        else if (i < C_ * K_ + K_)  g_counts[i - C_ * K_] = 0.f;
        else                        g_diff = 0.f;
    }
}

__global__ void __launch_bounds__(256, 1) vq_main(const float* __restrict__ inp,
                                                  const float* __restrict__ emb,
                                                  float* __restrict__ out)
{
    extern __shared__ float sm[];
    float* e_sh   = sm;                          // [K][EPAD]  (e_sh[k*EPAD + c])
    float* esq    = e_sh + K_ * EPAD;            // [K]
    float* x_sh   = esq + K_;                    // [W][XPAD]  (x_sh[w*XPAD + c])
    float* redv   = x_sh + W_ * XPAD;            // [64][8]
    int*   redk   = (int*)(redv + 64 * 8);       // [64][8]
    int*   ind_sh = redk + 64 * 8;               // [64]
    float* hist   = (float*)(ind_sh + 64);       // [K]
    float* diff_sh = hist + K_;                  // [1]

    const int tid  = threadIdx.x;
    const int lane = tid & 31;
    const int wid  = tid >> 5;

    // Load embedding [C][K] -> transposed e_sh[k][c] (pad-66: 2-way store conflicts only)
    for (int i = tid; i < C_ * K_; i += 256) {
        int c = i >> 9, k = i & (K_ - 1);
        e_sh[k * EPAD + c] = emb[i];
    }
    for (int i = tid; i < K_; i += 256) hist[i] = 0.f;
    if (tid == 0) *diff_sh = 0.f;
    __syncthreads();
    // ||e_k||^2
    for (int k = tid; k < K_; k += 256) {
        const float* ek = e_sh + k * EPAD;
        float s = 0.f;
        #pragma unroll
        for (int c = 0; c < C_; ++c) s += ek[c] * ek[c];
        esq[k] = s;
    }
    __syncthreads();

    float diff_acc = 0.f;

    for (int row = blockIdx.x; row < NROWS_; row += gridDim.x) {
        const int b = row >> 6;
        const int h = row & 63;
        const float* base = inp + (long long)b * CHW_ + h * W_;

        // Coalesced load of the 64-point x-tile: x_sh[w][c] = input[b,c,h,w]
        for (int i = tid; i < C_ * W_; i += 256) {
            int c = i >> 6, w = i & 63;
            x_sh[w * XPAD + c] = base[c * HW_ + w];
        }
        __syncthreads();

        // Each lane owns points (lane) and (lane+32); x resident in registers.
        ull x0[32], x1[32];
        {
            const ull* xp0 = (const ull*)(x_sh + lane * XPAD);
            const ull* xp1 = (const ull*)(x_sh + (lane + 32) * XPAD);
            #pragma unroll
            for (int j = 0; j < 32; ++j) { x0[j] = xp0[j]; x1[j] = xp1[j]; }
        }
        float xsq0 = 0.f, xsq1 = 0.f;
        #pragma unroll
        for (int j = 0; j < 32; ++j) {
            float2 a = u2f(x0[j]), c2 = u2f(x1[j]);
            xsq0 += a.x * a.x;  xsq0 += a.y * a.y;
            xsq1 += c2.x * c2.x; xsq1 += c2.y * c2.y;
        }

        float dmin0 = 3.4e38f, dmin1 = 3.4e38f;
        int kmin0 = 0, kmin1 = 0;
        const int kbase = wid << 6;   // warp scans codes [wid*64, wid*64+64)

        #pragma unroll 2
        for (int kk = 0; kk < 64; ++kk) {
            const int k = kbase + kk;
            const ull* ep = (const ull*)(e_sh + k * EPAD);  // broadcast reads
            ull s00 = 0ull, s01 = 0ull, s10 = 0ull, s11 = 0ull;
            #pragma unroll
            for (int j = 0; j < 32; j += 2) {
                ull ea = ep[j], eb = ep[j + 1];
                fma2(s00, x0[j],     ea);
                fma2(s10, x1[j],     ea);
                fma2(s01, x0[j + 1], eb);
                fma2(s11, x1[j + 1], eb);
            }
            float2 a0 = u2f(s00), b0 = u2f(s01);
            float2 a1 = u2f(s10), b1 = u2f(s11);
            float dot0 = (a0.x + a0.y) + (b0.x + b0.y);
            float dot1 = (a1.x + a1.y) + (b1.x + b1.y);
            float eq = esq[k];
            float d0 = (xsq0 - 2.f * dot0) + eq;   // same formula shape as reference
            float d1 = (xsq1 - 2.f * dot1) + eq;
            if (d0 < dmin0) { dmin0 = d0; kmin0 = k; }   // ascending k -> first-min ties
            if (d1 < dmin1) { dmin1 = d1; kmin1 = k; }
        }

        redv[lane * 8 + wid] = dmin0;        redk[lane * 8 + wid] = kmin0;
        redv[(lane + 32) * 8 + wid] = dmin1; redk[(lane + 32) * 8 + wid] = kmin1;
        __syncthreads();

        if (tid < 64) {
            float dm = redv[tid * 8]; int km = redk[tid * 8];
            #pragma unroll
            for (int j = 1; j < 8; ++j) {     // ascending warp id = ascending code range
                float d = redv[tid * 8 + j];
                int k2 = redk[tid * 8 + j];
                if (d < dm) { dm = d; km = k2; }
            }
            ind_sh[tid] = km;
            out[OFF_IND + (long long)row * W_ + tid] = (float)km;
            diff_acc += dm;                    // dm = ||x - e_k||^2 (incl. xsq)
            atomicAdd(&hist[km], 1.f);
        }
        __syncthreads();

        // Quantize output (STE form x + (q - x), matching reference arithmetic)
        // + scatter x into embedding_sum via global reduction atomics.
        float* outq = out + (long long)b * CHW_ + h * W_;
        for (int i = tid; i < C_ * W_; i += 256) {
            int c = i >> 6, w = i & 63;
            int k = ind_sh[w];
            float xv = x_sh[w * XPAD + c];
            float q  = e_sh[k * EPAD + c];
            outq[c * HW_ + w] = xv + (q - xv);
            atomicAdd(&g_esum[c * K_ + k], xv);
        }
        __syncthreads();
    }

    // block-level flush
    if (diff_acc != 0.f) atomicAdd(diff_sh, diff_acc);
    __syncthreads();
    if (tid == 0) atomicAdd(&g_diff, *diff_sh);
    for (int k = tid; k < K_; k += 256) {
        float hv = hist[k];
        if (hv != 0.f) atomicAdd(&g_counts[k], hv);
    }
}

__global__ void vq_finalize(const float* __restrict__ cs_in,
                            const float* __restrict__ avg_in,
                            float* __restrict__ out)
{
    __shared__ float red[512];
    const int k = threadIdx.x;
    float ncs = cs_in[k] * DECAYF + OMDF * g_counts[k];
    out[OFF_CS + k] = ncs;
    red[k] = ncs;
    __syncthreads();
    for (int s = 256; s > 0; s >>= 1) {
        if (k < s) red[k] += red[k + s];
        __syncthreads();
    }
    float n = red[0];
    float cs = (ncs + EPSF) / (n + 512.f * EPSF) * n;
    for (int c = 0; c < C_; ++c) {
        int idx = c * K_ + k;
        float av = avg_in[idx] * DECAYF + OMDF * g_esum[idx];
        out[OFF_AVG + idx] = av;
        out[OFF_EMB + idx] = av / cs;
    }
    if (k == 0) out[OFF_DIFF] = g_diff * (1.f / 16777216.f);  // exact *2^-24
}

extern "C" void kernel_launch(void* const* d_in, const int* in_sizes, int n_in,
                              void* d_out, int out_size)
{
    const float* inp = (const float*)d_in[0];   // input [B,C,H,W]
    const float* emb = (const float*)d_in[1];   // embedding [C,K]
    const float* cs  = (const float*)d_in[2];   // cluster_size [K]
    const float* avg = (const float*)d_in[3];   // embedding_avg [C,K]
    float* out = (float*)d_out;

    cudaFuncSetAttribute(vq_main, cudaFuncAttributeMaxDynamicSharedMemorySize, SMEM_BYTES);

    vq_init<<<132, 256>>>();
    vq_main<<<148, 256, SMEM_BYTES>>>(inp, emb, out);
    vq_finalize<<<1, 512>>>(cs, avg, out);
}

// round 6
// speedup vs baseline: 1.2575x; 1.2575x over previous
#include <cuda_runtime.h>
#include <cstdint>

#define DECAYF 0.99f
#define OMDF   0.01f
#define EPSF   1e-5f

constexpr int C_ = 64, K_ = 512, B_ = 64, H_ = 64, W_ = 64;
constexpr int HW_  = H_ * W_;          // 4096
constexpr int CHW_ = C_ * HW_;         // 262144
constexpr int NROWS_ = B_ * H_;        // 4096
constexpr int NPTS_  = NROWS_ * W_;    // 262144

// Output layout (concatenated float32, reference return order)
constexpr long long OFF_DIFF = (long long)B_ * C_ * H_ * W_;   // 16777216
constexpr long long OFF_IND  = OFF_DIFF + 1;
constexpr long long OFF_EMB  = OFF_IND + (long long)NPTS_;
constexpr long long OFF_CS   = OFF_EMB + (long long)C_ * K_;
constexpr long long OFF_AVG  = OFF_CS + K_;

// device scratch (no allocations allowed)
__device__ float g_esum[C_ * K_];
__device__ float g_counts[K_];
__device__ float g_diff;

// ---- SMEM float-offset layout for vq_main
constexpr int EP = 520;                      // e row stride (==8 mod 32: conflict-free B-frag loads)
constexpr int XP = 68;                       // x row stride (==4 mod 32: conflict-free A-frag loads)
constexpr int SM_E    = 0;                   // e_sh [64][520] fp32 (original embedding, [c][k])
constexpr int SM_ESQ  = 64 * EP;             // esq [512]
constexpr int SM_X    = SM_ESQ + K_;         // x_sh [64][68]  ([point][channel])
constexpr int SM_REDV = SM_X + 64 * XP;      // redv [64][8]
constexpr int SM_REDK = SM_REDV + 512;       // redk [64][8]
constexpr int SM_IND  = SM_REDK + 512;       // ind [64]
constexpr int SM_HIST = SM_IND + 64;         // hist [512]
constexpr int SM_DIFF = SM_HIST + K_;        // [1]
constexpr int SMEM_BYTES = (SM_DIFF + 1) * 4;   // ~159 KB

// m16n8k8 tf32 mma (legacy HMMA path — plain-PTX, valid on sm_100 base target)
__device__ __forceinline__ void mma8(float* d, const uint32_t* a, uint32_t b0, uint32_t b1) {
    asm volatile(
        "mma.sync.aligned.m16n8k8.row.col.f32.tf32.tf32.f32 "
        "{%0,%1,%2,%3}, {%4,%5,%6,%7}, {%8,%9}, {%0,%1,%2,%3};"
        : "+f"(d[0]), "+f"(d[1]), "+f"(d[2]), "+f"(d[3])
        : "r"(a[0]), "r"(a[1]), "r"(a[2]), "r"(a[3]), "r"(b0), "r"(b1));
}
// fp32 -> (tf32 hi, tf32 lo) split
__device__ __forceinline__ void cvt2(float v, uint32_t& hi, uint32_t& lo) {
    asm("cvt.rna.tf32.f32 %0, %1;" : "=r"(hi) : "f"(v));
    float l = v - __uint_as_float(hi);
    asm("cvt.rna.tf32.f32 %0, %1;" : "=r"(lo) : "f"(l));
}

__global__ void vq_init() {
    int i = blockIdx.x * blockDim.x + threadIdx.x;
    const int tot = C_ * K_ + K_ + 1;
    for (; i < tot; i += gridDim.x * blockDim.x) {
        if (i < C_ * K_)            g_esum[i] = 0.f;
        else if (i < C_ * K_ + K_)  g_counts[i - C_ * K_] = 0.f;
        else                        g_diff = 0.f;
    }
}

__global__ void __launch_bounds__(256, 1) vq_main(const float* __restrict__ inp,
                                                  const float* __restrict__ emb,
                                                  float* __restrict__ out)
{
    extern __shared__ float sm[];
    float* e_sh   = sm + SM_E;
    float* esq    = sm + SM_ESQ;
    float* x_sh   = sm + SM_X;
    float* redv   = sm + SM_REDV;
    int*   redk   = (int*)(sm + SM_REDK);
    int*   ind_sh = (int*)(sm + SM_IND);
    float* hist   = sm + SM_HIST;
    float* diff_sh = sm + SM_DIFF;

    const int tid = threadIdx.x, lane = tid & 31, wid = tid >> 5;
    const int g = lane >> 2, tig = lane & 3;   // mma groupID / threadID-in-group

    // embedding [C][K] row-major -> e_sh[c*EP + k] (coalesced, conflict-free store)
    for (int i = tid; i < C_ * K_; i += 256) {
        int c = i >> 9, k = i & (K_ - 1);
        e_sh[c * EP + k] = emb[i];
    }
    for (int i = tid; i < K_; i += 256) hist[i] = 0.f;
    if (tid == 0) *diff_sh = 0.f;
    __syncthreads();
    for (int k = tid; k < K_; k += 256) {
        float s = 0.f;
        #pragma unroll
        for (int c = 0; c < C_; ++c) { float v = e_sh[c * EP + k]; s += v * v; }
        esq[k] = s;
    }
    __syncthreads();

    // hoist 0.5*esq for this thread's 16 distance columns (fixed across row-tiles)
    float esqh[16];
    #pragma unroll
    for (int nt = 0; nt < 8; ++nt) {
        int k0 = wid * 64 + nt * 8 + 2 * tig;
        esqh[2 * nt]     = 0.5f * esq[k0];
        esqh[2 * nt + 1] = 0.5f * esq[k0 + 1];
    }

    float diff_acc = 0.f;

    for (int row = blockIdx.x; row < NROWS_; row += gridDim.x) {
        const int b = row >> 6, h = row & 63;
        const float* base = inp + (long long)b * CHW_ + h * W_;

        // coalesced x-tile load: x_sh[w][c] = input[b,c,h,w]
        for (int i = tid; i < C_ * W_; i += 256) {
            int c = i >> 6, w = i & 63;
            x_sh[w * XP + c] = base[c * HW_ + w];
        }
        __syncthreads();

        // D[64 pts x 64 codes-per-warp] via 3xTF32 mma. acc[mt][nt][frag]
        float acc[4][8][4];
        #pragma unroll
        for (int mt = 0; mt < 4; ++mt)
            #pragma unroll
            for (int nt = 0; nt < 8; ++nt)
                #pragma unroll
                for (int f = 0; f < 4; ++f) acc[mt][nt][f] = 0.f;

        for (int kk = 0; kk < 8; ++kk) {        // k-steps of 8 channels
            uint32_t ahi[4][4], alo[4][4];
            #pragma unroll
            for (int mt = 0; mt < 4; ++mt) {    // A frag: a0(r0,c0) a1(r1,c0) a2(r0,c1) a3(r1,c1)
                int r0 = 16 * mt + g, r1 = r0 + 8;
                int c0 = 8 * kk + tig, c1 = c0 + 4;
                cvt2(x_sh[r0 * XP + c0], ahi[mt][0], alo[mt][0]);
                cvt2(x_sh[r1 * XP + c0], ahi[mt][1], alo[mt][1]);
                cvt2(x_sh[r0 * XP + c1], ahi[mt][2], alo[mt][2]);
                cvt2(x_sh[r1 * XP + c1], ahi[mt][3], alo[mt][3]);
            }
            #pragma unroll
            for (int nt = 0; nt < 8; ++nt) {    // B frag: b0(k=tig,n=g), b1(k=tig+4,n=g)
                int col = wid * 64 + nt * 8 + g;
                uint32_t bh0, bl0, bh1, bl1;
                cvt2(e_sh[(8 * kk + tig) * EP + col], bh0, bl0);
                cvt2(e_sh[(8 * kk + tig + 4) * EP + col], bh1, bl1);
                #pragma unroll
                for (int mt = 0; mt < 4; ++mt) {
                    mma8(acc[mt][nt], ahi[mt], bh0, bh1);   // hi*hi
                    mma8(acc[mt][nt], ahi[mt], bl0, bl1);   // hi*lo
                    mma8(acc[mt][nt], alo[mt], bh0, bh1);   // lo*hi
                }
            }
        }

        // per-thread argmin over its 16 columns, 8 row-slots (rows 16mt+g, 16mt+8+g)
        float dmn[8]; int kmn[8];
        #pragma unroll
        for (int s = 0; s < 8; ++s) { dmn[s] = 3.4e38f; kmn[s] = 0; }
        #pragma unroll
        for (int mt = 0; mt < 4; ++mt)
            #pragma unroll
            for (int nt = 0; nt < 8; ++nt) {
                int k0 = wid * 64 + nt * 8 + 2 * tig;
                float d0 = esqh[2 * nt]     - acc[mt][nt][0];  // (r0, k0)
                float d1 = esqh[2 * nt + 1] - acc[mt][nt][1];  // (r0, k0+1)
                float d2 = esqh[2 * nt]     - acc[mt][nt][2];  // (r1, k0)
                float d3 = esqh[2 * nt + 1] - acc[mt][nt][3];  // (r1, k0+1)
                int s0 = 2 * mt, s1 = 2 * mt + 1;
                if (d0 < dmn[s0] || (d0 == dmn[s0] && k0     < kmn[s0])) { dmn[s0] = d0; kmn[s0] = k0; }
                if (d1 < dmn[s0] || (d1 == dmn[s0] && k0 + 1 < kmn[s0])) { dmn[s0] = d1; kmn[s0] = k0 + 1; }
                if (d2 < dmn[s1] || (d2 == dmn[s1] && k0     < kmn[s1])) { dmn[s1] = d2; kmn[s1] = k0; }
                if (d3 < dmn[s1] || (d3 == dmn[s1] && k0 + 1 < kmn[s1])) { dmn[s1] = d3; kmn[s1] = k0 + 1; }
            }
        // reduce across the 4 threads (tig) sharing the same rows
        #pragma unroll
        for (int off = 1; off <= 2; off <<= 1) {
            #pragma unroll
            for (int s = 0; s < 8; ++s) {
                float od = __shfl_xor_sync(0xffffffffu, dmn[s], off);
                int   ok = __shfl_xor_sync(0xffffffffu, kmn[s], off);
                if (od < dmn[s] || (od == dmn[s] && ok < kmn[s])) { dmn[s] = od; kmn[s] = ok; }
            }
        }
        if (tig == 0) {
            #pragma unroll
            for (int mt = 0; mt < 4; ++mt) {
                redv[(16 * mt + g) * 8 + wid]     = dmn[2 * mt];
                redk[(16 * mt + g) * 8 + wid]     = kmn[2 * mt];
                redv[(16 * mt + 8 + g) * 8 + wid] = dmn[2 * mt + 1];
                redk[(16 * mt + 8 + g) * 8 + wid] = kmn[2 * mt + 1];
            }
        }
        __syncthreads();

        if (tid < 64) {
            float dm = redv[tid * 8]; int km = redk[tid * 8];
            #pragma unroll
            for (int j = 1; j < 8; ++j) {
                float d = redv[tid * 8 + j]; int k2 = redk[tid * 8 + j];
                if (d < dm || (d == dm && k2 < km)) { dm = d; km = k2; }
            }
            ind_sh[tid] = km;
            out[OFF_IND + (long long)row * W_ + tid] = (float)km;
            atomicAdd(&hist[km], 1.f);
        }
        __syncthreads();

        // quantize (STE), exact fp32 diff, esum scatter — old embedding from e_sh
        float* outq = out + (long long)b * CHW_ + h * W_;
        for (int i = tid; i < C_ * W_; i += 256) {
            int c = i >> 6, w = i & 63;
            int k = ind_sh[w];
            float xv = x_sh[w * XP + c];
            float q  = e_sh[c * EP + k];
            outq[c * HW_ + w] = xv + (q - xv);
            float er = q - xv;
            diff_acc += er * er;
            atomicAdd(&g_esum[c * K_ + k], xv);
        }
        __syncthreads();
    }

    if (diff_acc != 0.f) atomicAdd(diff_sh, diff_acc);
    __syncthreads();
    if (tid == 0) atomicAdd(&g_diff, *diff_sh);
    for (int k = tid; k < K_; k += 256) {
        float hv = hist[k];
        if (hv != 0.f) atomicAdd(&g_counts[k], hv);
    }
}

__global__ void vq_finalize(const float* __restrict__ cs_in,
                            const float* __restrict__ avg_in,
                            float* __restrict__ out)
{
    __shared__ float red[512];
    const int k = threadIdx.x;
    float ncs = cs_in[k] * DECAYF + OMDF * g_counts[k];
    out[OFF_CS + k] = ncs;
    red[k] = ncs;
    __syncthreads();
    for (int s = 256; s > 0; s >>= 1) {
        if (k < s) red[k] += red[k + s];
        __syncthreads();
    }
    float n = red[0];
    float cs = (ncs + EPSF) / (n + 512.f * EPSF) * n;
    for (int c = 0; c < C_; ++c) {
        int idx = c * K_ + k;
        float av = avg_in[idx] * DECAYF + OMDF * g_esum[idx];
        out[OFF_AVG + idx] = av;
        out[OFF_EMB + idx] = av / cs;
    }
    if (k == 0) out[OFF_DIFF] = g_diff * (1.f / 16777216.f);  // exact *2^-24
}

extern "C" void kernel_launch(void* const* d_in, const int* in_sizes, int n_in,
                              void* d_out, int out_size)
{
    const float* inp = (const float*)d_in[0];   // input [B,C,H,W]
    const float* emb = (const float*)d_in[1];   // embedding [C,K]
    const float* cs  = (const float*)d_in[2];   // cluster_size [K]
    const float* avg = (const float*)d_in[3];   // embedding_avg [C,K]
    float* out = (float*)d_out;

    cudaFuncSetAttribute(vq_main, cudaFuncAttributeMaxDynamicSharedMemorySize, SMEM_BYTES);

    vq_init<<<132, 256>>>();
    vq_main<<<148, 256, SMEM_BYTES>>>(inp, emb, out);
    vq_finalize<<<1, 512>>>(cs, avg, out);
}